// round 15
// baseline (speedup 1.0000x reference)
#include <cuda_runtime.h>
#include <cuda_bf16.h>
#include <cstdint>
#include <math.h>

#define TEMP 0.0005f
#define B_   32
#define CMEL 80
#define CTXT 512
#define CATT 80
#define T1_  1600
#define T2_  400

typedef __nv_bfloat16 bf16;

// ---------------- scratch (device globals; no allocation) ----------------
__device__ float g_kb [B_ * CTXT];
__device__ float g_qb [B_ * CMEL];
__device__ bf16  g_keys3[3u * B_ * CTXT * T2_];
__device__ bf16  g_que3 [3u * B_ * CMEL * T1_];
__device__ bf16  g_pWk1[1024 * 1536];
__device__ bf16  g_pWk2[80 * 1024];
__device__ bf16  g_pWq1[160 * 240];
__device__ bf16  g_pWq2[80 * 160];
__device__ bf16  g_pWq3[80 * 80];
__device__ bf16  g_k1b[(size_t)B_ * 1024 * T2_];
__device__ bf16  g_q1b[(size_t)B_ * 160 * T1_];
__device__ bf16  g_q2b[(size_t)B_ * 80 * T1_];
__device__ bf16  g_kfb[(size_t)B_ * CATT * T2_];
__device__ bf16  g_qfb[(size_t)B_ * CATT * T1_];
__device__ float g_k2s[B_ * T2_];
__device__ float g_q2s[B_ * T1_];

// ---------------- speaker projection ----------------
__global__ void bias_proj_kernel(const float* __restrict__ se, const float* __restrict__ W,
                                 const float* __restrict__ bias, float* __restrict__ out,
                                 int Cin, int Cout)
{
    int b    = blockIdx.y;
    int co   = blockIdx.x * 8 + (threadIdx.x >> 5);
    int lane = threadIdx.x & 31;
    if (co >= Cout) return;
    const float* s = se + (size_t)b * Cin;
    const float* w = W  + (size_t)co * Cin;
    float acc = 0.f;
    for (int i = lane; i < Cin; i += 32) acc += s[i] * w[i];
    #pragma unroll
    for (int o = 16; o > 0; o >>= 1) acc += __shfl_xor_sync(0xffffffffu, acc, o);
    if (lane == 0) out[b * Cout + co] = acc + bias[co];
}

// ---------------- fused weight packing (all 5 weights, one launch) ----------------
#define NPK0 (1024 * 512 * 3)
#define NPK1 (160 * 80 * 3)
#define NPK2 (80 * 1024)
#define NPK3 (80 * 160)
#define NPK4 (80 * 80)
#define NPK_TOT (NPK0 + NPK1 + NPK2 + NPK3 + NPK4)

__global__ void pack_all_kernel(const float* __restrict__ Wk1, const float* __restrict__ Wq1,
                                const float* __restrict__ Wk2, const float* __restrict__ Wq2,
                                const float* __restrict__ Wq3,
                                bf16* __restrict__ pWk1, bf16* __restrict__ pWq1,
                                bf16* __restrict__ pWk2, bf16* __restrict__ pWq2,
                                bf16* __restrict__ pWq3)
{
    int i = blockIdx.x * 256 + threadIdx.x;
    if (i < NPK0) {
        const int Cin = 512;
        int co = i / (Cin * 3), r = i - co * Cin * 3;
        int ci = r / 3, d = r - ci * 3;
        pWk1[(size_t)co * Cin * 3 + d * Cin + ci] = __float2bfloat16(Wk1[i]);
        return;
    }
    i -= NPK0;
    if (i < NPK1) {
        const int Cin = 80;
        int co = i / (Cin * 3), r = i - co * Cin * 3;
        int ci = r / 3, d = r - ci * 3;
        pWq1[(size_t)co * Cin * 3 + d * Cin + ci] = __float2bfloat16(Wq1[i]);
        return;
    }
    i -= NPK1;
    if (i < NPK2) { pWk2[i] = __float2bfloat16(Wk2[i]); return; }
    i -= NPK2;
    if (i < NPK3) { pWq2[i] = __float2bfloat16(Wq2[i]); return; }
    i -= NPK3;
    if (i < NPK4) { pWq3[i] = __float2bfloat16(Wq3[i]); }
}

// ---------------- prep: biased + shifted inputs (3 taps) ----------------
__global__ void prep_x3_kernel(const float* __restrict__ x, const float* __restrict__ chb,
                               bf16* __restrict__ out, int Cin, int T)
{
    int bc = blockIdx.y;
    int t  = blockIdx.x * 256 + threadIdx.x;
    if (t >= T) return;
    float  ca = chb[bc];
    float  v  = x[(size_t)bc * T + t] + ca;
    bf16   bv = __float2bfloat16(v);
    size_t plane = (size_t)B_ * Cin * T;
    size_t base  = (size_t)bc * T;
    out[plane + base + t] = bv;                           // d=1 (center)
    if (t + 1 < T) out[base + t + 1] = bv;                // d=0
    if (t == 0)     out[base + 0] = __float2bfloat16(0.f);
    if (t >= 1)     out[2 * plane + base + t - 1] = bv;   // d=2
    if (t == T - 1) out[2 * plane + base + T - 1] = __float2bfloat16(0.f);
}

// ---------------- MMA helpers ----------------
__device__ __forceinline__ uint32_t smem_u32(const void* p) {
    return (uint32_t)__cvta_generic_to_shared(p);
}
__device__ __forceinline__ void ldsm_x4(uint32_t* r, uint32_t addr) {
    asm volatile("ldmatrix.sync.aligned.m8n8.x4.shared.b16 {%0,%1,%2,%3}, [%4];"
                 : "=r"(r[0]), "=r"(r[1]), "=r"(r[2]), "=r"(r[3]) : "r"(addr));
}
__device__ __forceinline__ void ldsm_x4_t(uint32_t* r, uint32_t addr) {
    asm volatile("ldmatrix.sync.aligned.m8n8.x4.trans.shared.b16 {%0,%1,%2,%3}, [%4];"
                 : "=r"(r[0]), "=r"(r[1]), "=r"(r[2]), "=r"(r[3]) : "r"(addr));
}
__device__ __forceinline__ void mma_bf16(float* c, const uint32_t* a, const uint32_t* b) {
    asm volatile("mma.sync.aligned.m16n8k16.row.col.f32.bf16.bf16.f32 "
                 "{%0,%1,%2,%3}, {%4,%5,%6,%7}, {%8,%9}, {%0,%1,%2,%3};"
                 : "+f"(c[0]), "+f"(c[1]), "+f"(c[2]), "+f"(c[3])
                 : "r"(a[0]), "r"(a[1]), "r"(a[2]), "r"(a[3]), "r"(b[0]), "r"(b[1]));
}
__device__ __forceinline__ void cp16(void* sdst, const void* gsrc, int sz) {
    asm volatile("cp.async.cg.shared.global [%0], [%1], 16, %2;"
                 :: "r"(smem_u32(sdst)), "l"(gsrc), "r"(sz) : "memory");
}

// ---------------- bf16 GEMM 128x128, flat-N across batches ----------------
// N dim = B_*T flattened (n = b*T + t). T % 8 == 0 so 8-elem segments stay in one batch.
// A: [Cout][Ktot] bf16.  X: TAPS==1 -> [B][Ktot][T]; TAPS==3 -> [3][B][Cin][T].
// 8 warps = 4(m) x 2(n); warp tile 32co x 64t; acc[2][8][4] per thread.
#define A_PITCH 72
#define B_PITCH 136
#define ABUF (128 * A_PITCH * 2)
#define BBUF (64 * B_PITCH * 2)
#define G_SMEM (2 * ABUF + 2 * BBUF)     // 71680 B

template<int TAPS, bool RELU>
__global__ __launch_bounds__(256)
void gemm128_kernel(const bf16* __restrict__ A, const bf16* __restrict__ X,
                    const float* __restrict__ bias, bf16* __restrict__ Y,
                    int Cin, int Cout, int Ktot, int T, int NT)
{
    extern __shared__ __align__(16) char sm_[];
    bf16* As = (bf16*)sm_;                    // [2][128][72]
    bf16* Bs = (bf16*)(sm_ + 2 * ABUF);       // [2][64][136]

    const int co0 = blockIdx.y * 128;
    const int n0  = blockIdx.x * 128;
    const int tid = threadIdx.x;
    const int lane = tid & 31, wid = tid >> 5;
    const int wm = wid >> 1, wn = wid & 1;
    const int NC = (Ktot + 63) >> 6;

    auto stage = [&](int c, int buf) {
        const int k0 = c << 6;
        bf16* Ab = As + buf * (128 * A_PITCH);
        bf16* Bb = Bs + buf * (64 * B_PITCH);
        #pragma unroll
        for (int i = 0; i < 4; i++) {        // A: 128 rows x 64 k
            int u    = tid + (i << 8);
            int row  = u >> 3;
            int segc = (u & 7) << 3;
            int kk   = k0 + segc;
            const bf16* src = A;
            int sz = 0;
            if ((co0 + row) < Cout && kk < Ktot) {
                src = A + (size_t)(co0 + row) * Ktot + kk;
                sz = 16;
            }
            cp16(Ab + row * A_PITCH + segc, src, sz);
        }
        #pragma unroll
        for (int i = 0; i < 4; i++) {        // B: 64 k-rows x 128 n
            int u    = tid + (i << 8);
            int krow = u >> 4;
            int nseg = (u & 15) << 3;
            int k    = k0 + krow;
            int n    = n0 + nseg;
            const bf16* src = X;
            int sz = 0;
            if (k < Ktot && n < NT) {
                int b = n / T;
                int t = n - b * T;
                if (TAPS == 3) {
                    int d  = (k >= 2 * Cin) ? 2 : ((k >= Cin) ? 1 : 0);
                    int ci = k - d * Cin;
                    src = X + ((size_t)(d * B_ + b) * Cin + ci) * T + t;
                } else {
                    src = X + ((size_t)b * Cin + k) * T + t;
                }
                sz = 16;
            }
            cp16(Bb + krow * B_PITCH + nseg, src, sz);
        }
        asm volatile("cp.async.commit_group;" ::: "memory");
    };

    float acc[2][8][4];
    #pragma unroll
    for (int m = 0; m < 2; m++)
        #pragma unroll
        for (int n = 0; n < 8; n++)
            #pragma unroll
            for (int r = 0; r < 4; r++) acc[m][n][r] = 0.f;

    const int lr = lane & 15, lh = lane >> 4;
    const uint32_t a_base = smem_u32(As + (wm * 32 + lr) * A_PITCH + lh * 8);
    const uint32_t b_base = smem_u32(Bs + lr * B_PITCH + wn * 64 + lh * 8);

    stage(0, 0);
    for (int c = 0; c < NC; c++) {
        const int buf = c & 1;
        if (c + 1 < NC) {
            stage(c + 1, buf ^ 1);
            asm volatile("cp.async.wait_group 1;" ::: "memory");
        } else {
            asm volatile("cp.async.wait_group 0;" ::: "memory");
        }
        __syncthreads();

        #pragma unroll
        for (int ks = 0; ks < 64; ks += 16) {
            uint32_t af[2][4];
            ldsm_x4(af[0], a_base + buf * ABUF + ks * 2);
            ldsm_x4(af[1], a_base + buf * ABUF + 16 * A_PITCH * 2 + ks * 2);
            uint32_t bfr[4][4];
            #pragma unroll
            for (int j = 0; j < 4; j++)
                ldsm_x4_t(bfr[j], b_base + buf * BBUF + ks * (B_PITCH * 2) + j * 32);
            #pragma unroll
            for (int m = 0; m < 2; m++)
                #pragma unroll
                for (int j = 0; j < 4; j++) {
                    mma_bf16(acc[m][2 * j],     af[m], bfr[j]);
                    mma_bf16(acc[m][2 * j + 1], af[m], bfr[j] + 2);
                }
        }
        __syncthreads();
    }

    // epilogue (bf16 out); pairs (n, n+1) stay in one batch since c2 is even and T is even
    const int g  = lane >> 2;
    const int c2 = (lane & 3) << 1;
    #pragma unroll
    for (int m = 0; m < 2; m++) {
        #pragma unroll
        for (int nn = 0; nn < 8; nn++) {
            int n = n0 + wn * 64 + nn * 8 + c2;
            if (n >= NT) continue;
            int b = n / T;
            int t = n - b * T;
            #pragma unroll
            for (int h = 0; h < 2; h++) {
                int rr = co0 + wm * 32 + m * 16 + h * 8 + g;
                if (rr >= Cout) continue;
                float bvs = bias[rr];
                float v0 = acc[m][nn][h * 2 + 0] + bvs;
                float v1 = acc[m][nn][h * 2 + 1] + bvs;
                if (RELU) { v0 = fmaxf(v0, 0.f); v1 = fmaxf(v1, 0.f); }
                __nv_bfloat162 p = __floats2bfloat162_rn(v0, v1);
                *(__nv_bfloat162*)(Y + ((size_t)b * Cout + rr) * T + t) = p;
            }
        }
    }
}

// ---------------- fused sum-of-squares for k and q ----------------
__global__ void sumsq_both_kernel(const bf16* __restrict__ kfb, const bf16* __restrict__ qfb,
                                  float* __restrict__ k2s, float* __restrict__ q2s)
{
    int b = blockIdx.y;
    int t = blockIdx.x * 256 + threadIdx.x;
    if (t < T2_) {
        const bf16* xb = kfb + (size_t)b * CATT * T2_;
        float s = 0.f;
        #pragma unroll 8
        for (int c = 0; c < CATT; c++) {
            float v = __bfloat162float(xb[(size_t)c * T2_ + t]);
            s += v * v;
        }
        k2s[b * T2_ + t] = s;
    } else if (t - T2_ < T1_) {
        int tq = t - T2_;
        const bf16* xb = qfb + (size_t)b * CATT * T1_;
        float s = 0.f;
        #pragma unroll 8
        for (int c = 0; c < CATT; c++) {
            float v = __bfloat162float(xb[(size_t)c * T1_ + tq]);
            s += v * v;
        }
        q2s[b * T1_ + tq] = s;
    }
}

// ---------------- attn: MMA qk + fused double softmax ----------------
#define KS_PITCH 408
#define SC_PITCH 416
#define ATTN_SMEM (80 * KS_PITCH * 2 + 80 * 40 * 2)

__global__ __launch_bounds__(256)
void attn_mma_kernel(const bf16* __restrict__ qfb, const bf16* __restrict__ kfb,
                     const float* __restrict__ q2s, const float* __restrict__ k2s,
                     const float* __restrict__ prior, const int* __restrict__ msk_in,
                     float* __restrict__ attn_out, float* __restrict__ logp_out)
{
    extern __shared__ __align__(16) char sm_[];
    bf16*  Ks = (bf16*)sm_;                           // [80][408]
    bf16*  Qs = (bf16*)(sm_ + 80 * KS_PITCH * 2);     // [80][40]
    float* Sc = (float*)sm_;                          // [32][416] overlay

    const int b   = blockIdx.y;
    const int t0  = blockIdx.x * 32;
    const int tid = threadIdx.x;
    const int lane = tid & 31, w = tid >> 5;
    const float NINF = __int_as_float(0xff800000u);

    const bf16* kbp = kfb + (size_t)b * 80 * 400;
    for (int i = tid; i < 80 * 50; i += 256) {
        int c = i / 50, s8 = (i - c * 50) * 8;
        *(uint4*)&Ks[c * KS_PITCH + s8] = *(const uint4*)&kbp[c * 400 + s8];
    }
    if (tid < 80) *(uint4*)&Ks[tid * KS_PITCH + 400] = make_uint4(0, 0, 0, 0);
    const bf16* qbp = qfb + (size_t)b * 80 * 1600 + t0;
    for (int i = tid; i < 80 * 4; i += 256) {
        int c = i >> 2, s8 = (i & 3) * 8;
        *(uint4*)&Qs[c * 40 + s8] = *(const uint4*)&qbp[(size_t)c * 1600 + s8];
    }
    __syncthreads();

    const int m0    = (w & 1) * 16;
    const int nbase = (w >> 1) * 104;
    float acc[13][4];
    #pragma unroll
    for (int j = 0; j < 13; j++)
        #pragma unroll
        for (int r = 0; r < 4; r++) acc[j][r] = 0.f;

    const int lr2 = lane & 7, selA = (lane >> 3) & 1, khA = lane >> 4;
    const int lrB = lane & 15, lhB = lane >> 4;

    #pragma unroll
    for (int ks = 0; ks < 5; ks++) {
        uint32_t af[4];
        ldsm_x4_t(af, smem_u32(Qs + (ks * 16 + khA * 8 + lr2) * 40 + m0 + selA * 8));
        #pragma unroll
        for (int jj = 0; jj < 7; jj++) {
            uint32_t bfr[4];
            ldsm_x4_t(bfr, smem_u32(Ks + (ks * 16 + lrB) * KS_PITCH + nbase + jj * 16 + lhB * 8));
            mma_bf16(acc[2 * jj], af, bfr);
            if (2 * jj + 1 < 13) mma_bf16(acc[2 * jj + 1], af, bfr + 2);
        }
    }
    __syncthreads();

    const int g  = lane >> 2;
    const int c2 = (lane & 3) << 1;
    #pragma unroll
    for (int j = 0; j < 13; j++) {
        int col = nbase + j * 8 + c2;
        *(float2*)&Sc[(m0 + g) * SC_PITCH + col]     = make_float2(acc[j][0], acc[j][1]);
        *(float2*)&Sc[(m0 + 8 + g) * SC_PITCH + col] = make_float2(acc[j][2], acc[j][3]);
    }
    __syncthreads();

    float k2v[13];
    int   mv[13];
    #pragma unroll
    for (int j = 0; j < 13; j++) {
        int s = lane + 32 * j;
        k2v[j] = (s < 400) ? k2s[b * 400 + s] : 0.f;
        mv[j]  = (s < 400) ? msk_in[b * 400 + s] : 1;
    }

    #pragma unroll
    for (int rr = 0; rr < 4; rr++) {
        const int trow = 4 * w + rr;
        const int t    = t0 + trow;
        const float q2v = q2s[b * 1600 + t];

        float x[13], e[13];
        float mx = NINF;
        #pragma unroll
        for (int j = 0; j < 13; j++) {
            int s = lane + 32 * j;
            float qk = Sc[trow * SC_PITCH + s];
            x[j] = (s < 400) ? (-TEMP * (q2v + k2v[j] - 2.f * qk)) : NINF;
            mx = fmaxf(mx, x[j]);
        }
        #pragma unroll
        for (int o = 16; o > 0; o >>= 1) mx = fmaxf(mx, __shfl_xor_sync(0xffffffffu, mx, o));

        float se = 0.f;
        #pragma unroll
        for (int j = 0; j < 13; j++) {
            e[j] = __expf(x[j] - mx);
            se += e[j];
        }
        #pragma unroll
        for (int o = 16; o > 0; o >>= 1) se += __shfl_xor_sync(0xffffffffu, se, o);
        const float lse_m = __logf(se);

        const float* pr = prior    + ((size_t)b * 1600 + t) * 400;
        float* lp_out   = logp_out + ((size_t)b * 1600 + t) * 400;
        float* at_out   = attn_out + ((size_t)b * 1600 + t) * 400;

        float s2 = 0.f;
        #pragma unroll
        for (int j = 0; j < 13; j++) {
            int s = lane + 32 * j;
            if (s < 400) {
                float pv = pr[s] + 1e-8f;
                float lp = x[j] - mx - lse_m + __logf(pv);
                lp_out[s] = lp;
                e[j] = mv[j] ? 0.f : e[j] * pv;
            } else {
                e[j] = 0.f;
            }
            s2 += e[j];
        }
        #pragma unroll
        for (int o = 16; o > 0; o >>= 1) s2 += __shfl_xor_sync(0xffffffffu, s2, o);
        const float inv = 1.f / s2;
        #pragma unroll
        for (int j = 0; j < 13; j++) {
            int s = lane + 32 * j;
            if (s < 400) at_out[s] = e[j] * inv;
        }
    }
}

// ---------------- launch ----------------
extern "C" void kernel_launch(void* const* d_in, const int* in_sizes, int n_in,
                              void* d_out, int out_size)
{
    const float* queries = (const float*)d_in[0];
    const float* keys    = (const float*)d_in[1];
    const int*   mask    = (const int*)d_in[2];
    const float* prior   = (const float*)d_in[3];
    const float* se      = (const float*)d_in[4];
    const float* Wk1     = (const float*)d_in[5];
    const float* bk1     = (const float*)d_in[6];
    const float* Wk2     = (const float*)d_in[7];
    const float* bk2     = (const float*)d_in[8];
    const float* Wq1     = (const float*)d_in[9];
    const float* bq1     = (const float*)d_in[10];
    const float* Wq2     = (const float*)d_in[11];
    const float* bq2     = (const float*)d_in[12];
    const float* Wq3     = (const float*)d_in[13];
    const float* bq3     = (const float*)d_in[14];
    const float* Wks     = (const float*)d_in[15];
    const float* bks     = (const float*)d_in[16];
    const float* Wqs     = (const float*)d_in[17];
    const float* bqs     = (const float*)d_in[18];
    float* out = (float*)d_out;

    float *kb, *qb, *k2s, *q2s;
    bf16 *keys3, *que3, *pWk1, *pWk2, *pWq1, *pWq2, *pWq3, *k1b, *q1b, *q2b, *kfb, *qfb;
    cudaGetSymbolAddress((void**)&kb,    g_kb);
    cudaGetSymbolAddress((void**)&qb,    g_qb);
    cudaGetSymbolAddress((void**)&keys3, g_keys3);
    cudaGetSymbolAddress((void**)&que3,  g_que3);
    cudaGetSymbolAddress((void**)&pWk1,  g_pWk1);
    cudaGetSymbolAddress((void**)&pWk2,  g_pWk2);
    cudaGetSymbolAddress((void**)&pWq1,  g_pWq1);
    cudaGetSymbolAddress((void**)&pWq2,  g_pWq2);
    cudaGetSymbolAddress((void**)&pWq3,  g_pWq3);
    cudaGetSymbolAddress((void**)&k1b,   g_k1b);
    cudaGetSymbolAddress((void**)&q1b,   g_q1b);
    cudaGetSymbolAddress((void**)&q2b,   g_q2b);
    cudaGetSymbolAddress((void**)&kfb,   g_kfb);
    cudaGetSymbolAddress((void**)&qfb,   g_qfb);
    cudaGetSymbolAddress((void**)&k2s,   g_k2s);
    cudaGetSymbolAddress((void**)&q2s,   g_q2s);

    float* attn_out = out;
    float* logp_out = out + (size_t)B_ * T1_ * T2_;

    // attribute setup (idempotent, graph-safe)
    cudaFuncSetAttribute(gemm128_kernel<3, true>,  cudaFuncAttributeMaxDynamicSharedMemorySize, G_SMEM);
    cudaFuncSetAttribute(gemm128_kernel<1, true>,  cudaFuncAttributeMaxDynamicSharedMemorySize, G_SMEM);
    cudaFuncSetAttribute(gemm128_kernel<1, false>, cudaFuncAttributeMaxDynamicSharedMemorySize, G_SMEM);
    cudaFuncSetAttribute(attn_mma_kernel, cudaFuncAttributeMaxDynamicSharedMemorySize, ATTN_SMEM);

    // launches 0-4 (prep; ncu -s 5 lands on the Wk1 GEMM below)
    bias_proj_kernel<<<dim3(CTXT / 8, B_), 256>>>(se, Wks, bks, kb, CTXT, CTXT);                 // 0
    bias_proj_kernel<<<dim3((CMEL + 7) / 8, B_), 256>>>(se, Wqs, bqs, qb, CTXT, CMEL);           // 1
    pack_all_kernel<<<(NPK_TOT + 255) / 256, 256>>>(Wk1, Wq1, Wk2, Wq2, Wq3,
                                                    pWk1, pWq1, pWk2, pWq2, pWq3);               // 2
    prep_x3_kernel<<<dim3((T2_ + 255) / 256, B_ * CTXT), 256>>>(keys, kb, keys3, CTXT, T2_);     // 3
    prep_x3_kernel<<<dim3((T1_ + 255) / 256, B_ * CMEL), 256>>>(queries, qb, que3, CMEL, T1_);   // 4

    const int NT2 = B_ * T2_;   // 12800
    const int NT1 = B_ * T1_;   // 51200

    // key path (flat-N)
    gemm128_kernel<3, true ><<<dim3(NT2 / 128, 8), 256, G_SMEM>>>(pWk1, keys3, bk1, k1b, CTXT, 1024, 1536, T2_, NT2);  // 5 (profiled)
    gemm128_kernel<1, false><<<dim3(NT2 / 128, 1), 256, G_SMEM>>>(pWk2, k1b, bk2, kfb, 1024, 80, 1024, T2_, NT2);      // 6

    // query path (flat-N)
    gemm128_kernel<3, true ><<<dim3(NT1 / 128, 2), 256, G_SMEM>>>(pWq1, que3, bq1, q1b, CMEL, 160, 240, T1_, NT1);     // 7
    gemm128_kernel<1, true ><<<dim3(NT1 / 128, 1), 256, G_SMEM>>>(pWq2, q1b, bq2, q2b, 160, 80, 160, T1_, NT1);        // 8
    gemm128_kernel<1, false><<<dim3(NT1 / 128, 1), 256, G_SMEM>>>(pWq3, q2b, bq3, qfb, 80, 80, 80, T1_, NT1);          // 9

    // norms (fused)
    sumsq_both_kernel<<<dim3((T2_ + T1_ + 255) / 256, B_), 256>>>(kfb, qfb, k2s, q2s);           // 10

    // fused attention epilogue (tensor-core qk)
    attn_mma_kernel<<<dim3(T1_ / 32, B_), 256, ATTN_SMEM>>>(qfb, kfb, q2s, k2s, prior, mask, attn_out, logp_out);      // 11
}

// round 16
// speedup vs baseline: 1.1292x; 1.1292x over previous
#include <cuda_runtime.h>
#include <cuda_bf16.h>
#include <cstdint>
#include <math.h>

#define TEMP 0.0005f
#define B_   32
#define CMEL 80
#define CTXT 512
#define CATT 80
#define T1_  1600
#define T2_  400

typedef __nv_bfloat16 bf16;

// ---------------- scratch (device globals; no allocation) ----------------
__device__ float g_kb [B_ * CTXT];
__device__ float g_qb [B_ * CMEL];
__device__ bf16  g_keys3[3u * B_ * CTXT * T2_];
__device__ bf16  g_que3 [3u * B_ * CMEL * T1_];
__device__ bf16  g_pWk1[1024 * 1536];
__device__ bf16  g_pWk2[80 * 1024];
__device__ bf16  g_pWq1[160 * 240];
__device__ bf16  g_pWq2[80 * 160];
__device__ bf16  g_pWq3[80 * 80];
__device__ bf16  g_k1b[(size_t)B_ * 1024 * T2_];
__device__ bf16  g_q1b[(size_t)B_ * 160 * T1_];
__device__ bf16  g_q2b[(size_t)B_ * 80 * T1_];
__device__ bf16  g_kfb[(size_t)B_ * CATT * T2_];
__device__ bf16  g_qfb[(size_t)B_ * CATT * T1_];
__device__ float g_k2s[B_ * T2_];
__device__ float g_q2s[B_ * T1_];

// ---------------- speaker projection ----------------
__global__ void bias_proj_kernel(const float* __restrict__ se, const float* __restrict__ W,
                                 const float* __restrict__ bias, float* __restrict__ out,
                                 int Cin, int Cout)
{
    int b    = blockIdx.y;
    int co   = blockIdx.x * 8 + (threadIdx.x >> 5);
    int lane = threadIdx.x & 31;
    if (co >= Cout) return;
    const float* s = se + (size_t)b * Cin;
    const float* w = W  + (size_t)co * Cin;
    float acc = 0.f;
    for (int i = lane; i < Cin; i += 32) acc += s[i] * w[i];
    #pragma unroll
    for (int o = 16; o > 0; o >>= 1) acc += __shfl_xor_sync(0xffffffffu, acc, o);
    if (lane == 0) out[b * Cout + co] = acc + bias[co];
}

// ---------------- fused weight packing (all 5 weights, one launch) ----------------
#define NPK0 (1024 * 512 * 3)
#define NPK1 (160 * 80 * 3)
#define NPK2 (80 * 1024)
#define NPK3 (80 * 160)
#define NPK4 (80 * 80)
#define NPK_TOT (NPK0 + NPK1 + NPK2 + NPK3 + NPK4)

__global__ void pack_all_kernel(const float* __restrict__ Wk1, const float* __restrict__ Wq1,
                                const float* __restrict__ Wk2, const float* __restrict__ Wq2,
                                const float* __restrict__ Wq3,
                                bf16* __restrict__ pWk1, bf16* __restrict__ pWq1,
                                bf16* __restrict__ pWk2, bf16* __restrict__ pWq2,
                                bf16* __restrict__ pWq3)
{
    int i = blockIdx.x * 256 + threadIdx.x;
    if (i < NPK0) {
        const int Cin = 512;
        int co = i / (Cin * 3), r = i - co * Cin * 3;
        int ci = r / 3, d = r - ci * 3;
        pWk1[(size_t)co * Cin * 3 + d * Cin + ci] = __float2bfloat16(Wk1[i]);
        return;
    }
    i -= NPK0;
    if (i < NPK1) {
        const int Cin = 80;
        int co = i / (Cin * 3), r = i - co * Cin * 3;
        int ci = r / 3, d = r - ci * 3;
        pWq1[(size_t)co * Cin * 3 + d * Cin + ci] = __float2bfloat16(Wq1[i]);
        return;
    }
    i -= NPK1;
    if (i < NPK2) { pWk2[i] = __float2bfloat16(Wk2[i]); return; }
    i -= NPK2;
    if (i < NPK3) { pWq2[i] = __float2bfloat16(Wq2[i]); return; }
    i -= NPK3;
    if (i < NPK4) { pWq3[i] = __float2bfloat16(Wq3[i]); }
}

// ---------------- prep: biased + 3 shifted tap planes, vectorized (8 t per thread) -----
// out[d][bc][t] = bf16(x[bc][t + d - 1] + chb[bc]), zero outside [0,T).
// Shift realized by shifting the SOURCE window; all stores are aligned uint4.
template<int T, int CIN>
__global__ void prep_x3v_kernel(const float* __restrict__ x, const float* __restrict__ chb,
                                bf16* __restrict__ out)
{
    constexpr int NG = T / 8;
    int g = blockIdx.x * 256 + threadIdx.x;
    if (g >= B_ * CIN * NG) return;
    int bc = g / NG;
    int t0 = (g - bc * NG) * 8;
    float ca = chb[bc];
    const float* xr = x + (size_t)bc * T;

    float v[10];                               // covers t0-1 .. t0+8
    #pragma unroll
    for (int j = 0; j < 10; j++) {
        int t = t0 - 1 + j;
        v[j] = (t >= 0 && t < T) ? (xr[t] + ca) : 0.f;
    }

    auto pack4 = [](const float* p) {
        __nv_bfloat162 a0 = __floats2bfloat162_rn(p[0], p[1]);
        __nv_bfloat162 a1 = __floats2bfloat162_rn(p[2], p[3]);
        __nv_bfloat162 a2 = __floats2bfloat162_rn(p[4], p[5]);
        __nv_bfloat162 a3 = __floats2bfloat162_rn(p[6], p[7]);
        uint4 u;
        u.x = *(uint32_t*)&a0; u.y = *(uint32_t*)&a1;
        u.z = *(uint32_t*)&a2; u.w = *(uint32_t*)&a3;
        return u;
    };

    const size_t plane = (size_t)B_ * CIN * T;
    const size_t base  = (size_t)bc * T + t0;
    *(uint4*)&out[base]             = pack4(v + 0);   // d=0: x[t-1]
    *(uint4*)&out[plane + base]     = pack4(v + 1);   // d=1: x[t]
    *(uint4*)&out[2 * plane + base] = pack4(v + 2);   // d=2: x[t+1]
}

// ---------------- MMA helpers ----------------
__device__ __forceinline__ uint32_t smem_u32(const void* p) {
    return (uint32_t)__cvta_generic_to_shared(p);
}
__device__ __forceinline__ void ldsm_x4(uint32_t* r, uint32_t addr) {
    asm volatile("ldmatrix.sync.aligned.m8n8.x4.shared.b16 {%0,%1,%2,%3}, [%4];"
                 : "=r"(r[0]), "=r"(r[1]), "=r"(r[2]), "=r"(r[3]) : "r"(addr));
}
__device__ __forceinline__ void ldsm_x4_t(uint32_t* r, uint32_t addr) {
    asm volatile("ldmatrix.sync.aligned.m8n8.x4.trans.shared.b16 {%0,%1,%2,%3}, [%4];"
                 : "=r"(r[0]), "=r"(r[1]), "=r"(r[2]), "=r"(r[3]) : "r"(addr));
}
__device__ __forceinline__ void mma_bf16(float* c, const uint32_t* a, const uint32_t* b) {
    asm volatile("mma.sync.aligned.m16n8k16.row.col.f32.bf16.bf16.f32 "
                 "{%0,%1,%2,%3}, {%4,%5,%6,%7}, {%8,%9}, {%0,%1,%2,%3};"
                 : "+f"(c[0]), "+f"(c[1]), "+f"(c[2]), "+f"(c[3])
                 : "r"(a[0]), "r"(a[1]), "r"(a[2]), "r"(a[3]), "r"(b[0]), "r"(b[1]));
}
__device__ __forceinline__ void cp16(void* sdst, const void* gsrc, int sz) {
    asm volatile("cp.async.cg.shared.global [%0], [%1], 16, %2;"
                 :: "r"(smem_u32(sdst)), "l"(gsrc), "r"(sz) : "memory");
}

// ---------------- bf16 GEMM 128x128, K-chunk 64, 2-stage cp.async (r13 form) ----------
// A: [Cout][Ktot] bf16.  X: TAPS==1 -> [B][Ktot][T]; TAPS==3 -> [3][B][Cin][T].
// 8 warps = 4(m) x 2(n); warp tile 32co x 64t; acc[2][8][4] per thread.
#define A_PITCH 72
#define B_PITCH 136
#define ABUF (128 * A_PITCH * 2)
#define BBUF (64 * B_PITCH * 2)
#define G_SMEM (2 * ABUF + 2 * BBUF)     // 71680 B

template<int TAPS, bool RELU>
__global__ __launch_bounds__(256)
void gemm128_kernel(const bf16* __restrict__ A, const bf16* __restrict__ X,
                    const float* __restrict__ bias, bf16* __restrict__ Y,
                    int Cin, int Cout, int Ktot, int T)
{
    extern __shared__ __align__(16) char sm_[];
    bf16* As = (bf16*)sm_;                    // [2][128][72]
    bf16* Bs = (bf16*)(sm_ + 2 * ABUF);       // [2][64][136]

    const int b   = blockIdx.z;
    const int co0 = blockIdx.y * 128;
    const int t0  = blockIdx.x * 128;
    const int tid = threadIdx.x;
    const int lane = tid & 31, wid = tid >> 5;
    const int wm = wid >> 1, wn = wid & 1;
    const int NC = (Ktot + 63) >> 6;

    auto stage = [&](int c, int buf) {
        const int k0 = c << 6;
        bf16* Ab = As + buf * (128 * A_PITCH);
        bf16* Bb = Bs + buf * (64 * B_PITCH);
        #pragma unroll
        for (int i = 0; i < 4; i++) {        // A: 128 rows x 64 k
            int u    = tid + (i << 8);
            int row  = u >> 3;
            int segc = (u & 7) << 3;
            int kk   = k0 + segc;
            const bf16* src = A;
            int sz = 0;
            if ((co0 + row) < Cout && kk < Ktot) {
                src = A + (size_t)(co0 + row) * Ktot + kk;
                sz = 16;
            }
            cp16(Ab + row * A_PITCH + segc, src, sz);
        }
        #pragma unroll
        for (int i = 0; i < 4; i++) {        // B: 64 k-rows x 128 t
            int u    = tid + (i << 8);
            int krow = u >> 4;
            int tseg = (u & 15) << 3;
            int k    = k0 + krow;
            int tg   = t0 + tseg;
            const bf16* src = X;
            int sz = 0;
            if (k < Ktot && tg < T) {
                if (TAPS == 3) {
                    int d  = (k >= 2 * Cin) ? 2 : ((k >= Cin) ? 1 : 0);
                    int ci = k - d * Cin;
                    src = X + ((size_t)(d * B_ + b) * Cin + ci) * T + tg;
                } else {
                    src = X + ((size_t)b * Cin + k) * T + tg;
                }
                sz = 16;
            }
            cp16(Bb + krow * B_PITCH + tseg, src, sz);
        }
        asm volatile("cp.async.commit_group;" ::: "memory");
    };

    float acc[2][8][4];
    #pragma unroll
    for (int m = 0; m < 2; m++)
        #pragma unroll
        for (int n = 0; n < 8; n++)
            #pragma unroll
            for (int r = 0; r < 4; r++) acc[m][n][r] = 0.f;

    const int lr = lane & 15, lh = lane >> 4;
    const uint32_t a_base = smem_u32(As + (wm * 32 + lr) * A_PITCH + lh * 8);
    const uint32_t b_base = smem_u32(Bs + lr * B_PITCH + wn * 64 + lh * 8);

    stage(0, 0);
    for (int c = 0; c < NC; c++) {
        const int buf = c & 1;
        if (c + 1 < NC) {
            stage(c + 1, buf ^ 1);
            asm volatile("cp.async.wait_group 1;" ::: "memory");
        } else {
            asm volatile("cp.async.wait_group 0;" ::: "memory");
        }
        __syncthreads();

        #pragma unroll
        for (int ks = 0; ks < 64; ks += 16) {
            uint32_t af[2][4];
            ldsm_x4(af[0], a_base + buf * ABUF + ks * 2);
            ldsm_x4(af[1], a_base + buf * ABUF + 16 * A_PITCH * 2 + ks * 2);
            uint32_t bfr[4][4];
            #pragma unroll
            for (int j = 0; j < 4; j++)
                ldsm_x4_t(bfr[j], b_base + buf * BBUF + ks * (B_PITCH * 2) + j * 32);
            #pragma unroll
            for (int m = 0; m < 2; m++)
                #pragma unroll
                for (int j = 0; j < 4; j++) {
                    mma_bf16(acc[m][2 * j],     af[m], bfr[j]);
                    mma_bf16(acc[m][2 * j + 1], af[m], bfr[j] + 2);
                }
        }
        __syncthreads();
    }

    // epilogue (bf16 out)
    const int g  = lane >> 2;
    const int c2 = (lane & 3) << 1;
    #pragma unroll
    for (int m = 0; m < 2; m++) {
        #pragma unroll
        for (int n = 0; n < 8; n++) {
            int col = t0 + wn * 64 + n * 8 + c2;
            if (col >= T) continue;
            #pragma unroll
            for (int h = 0; h < 2; h++) {
                int rr = co0 + wm * 32 + m * 16 + h * 8 + g;
                if (rr >= Cout) continue;
                float bvs = bias[rr];
                float v0 = acc[m][n][h * 2 + 0] + bvs;
                float v1 = acc[m][n][h * 2 + 1] + bvs;
                if (RELU) { v0 = fmaxf(v0, 0.f); v1 = fmaxf(v1, 0.f); }
                __nv_bfloat162 p = __floats2bfloat162_rn(v0, v1);
                *(__nv_bfloat162*)(Y + ((size_t)b * Cout + rr) * T + col) = p;
            }
        }
    }
}

// ---------------- fused sum-of-squares for k and q ----------------
__global__ void sumsq_both_kernel(const bf16* __restrict__ kfb, const bf16* __restrict__ qfb,
                                  float* __restrict__ k2s, float* __restrict__ q2s)
{
    int b = blockIdx.y;
    int t = blockIdx.x * 256 + threadIdx.x;
    if (t < T2_) {
        const bf16* xb = kfb + (size_t)b * CATT * T2_;
        float s = 0.f;
        #pragma unroll 8
        for (int c = 0; c < CATT; c++) {
            float v = __bfloat162float(xb[(size_t)c * T2_ + t]);
            s += v * v;
        }
        k2s[b * T2_ + t] = s;
    } else if (t - T2_ < T1_) {
        int tq = t - T2_;
        const bf16* xb = qfb + (size_t)b * CATT * T1_;
        float s = 0.f;
        #pragma unroll 8
        for (int c = 0; c < CATT; c++) {
            float v = __bfloat162float(xb[(size_t)c * T1_ + tq]);
            s += v * v;
        }
        q2s[b * T1_ + tq] = s;
    }
}

// ---------------- attn: MMA qk + fused double softmax ----------------
#define KS_PITCH 408
#define SC_PITCH 416
#define ATTN_SMEM (80 * KS_PITCH * 2 + 80 * 40 * 2)

__global__ __launch_bounds__(256)
void attn_mma_kernel(const bf16* __restrict__ qfb, const bf16* __restrict__ kfb,
                     const float* __restrict__ q2s, const float* __restrict__ k2s,
                     const float* __restrict__ prior, const int* __restrict__ msk_in,
                     float* __restrict__ attn_out, float* __restrict__ logp_out)
{
    extern __shared__ __align__(16) char sm_[];
    bf16*  Ks = (bf16*)sm_;                           // [80][408]
    bf16*  Qs = (bf16*)(sm_ + 80 * KS_PITCH * 2);     // [80][40]
    float* Sc = (float*)sm_;                          // [32][416] overlay

    const int b   = blockIdx.y;
    const int t0  = blockIdx.x * 32;
    const int tid = threadIdx.x;
    const int lane = tid & 31, w = tid >> 5;
    const float NINF = __int_as_float(0xff800000u);

    const bf16* kbp = kfb + (size_t)b * 80 * 400;
    for (int i = tid; i < 80 * 50; i += 256) {
        int c = i / 50, s8 = (i - c * 50) * 8;
        *(uint4*)&Ks[c * KS_PITCH + s8] = *(const uint4*)&kbp[c * 400 + s8];
    }
    if (tid < 80) *(uint4*)&Ks[tid * KS_PITCH + 400] = make_uint4(0, 0, 0, 0);
    const bf16* qbp = qfb + (size_t)b * 80 * 1600 + t0;
    for (int i = tid; i < 80 * 4; i += 256) {
        int c = i >> 2, s8 = (i & 3) * 8;
        *(uint4*)&Qs[c * 40 + s8] = *(const uint4*)&qbp[(size_t)c * 1600 + s8];
    }
    __syncthreads();

    const int m0    = (w & 1) * 16;
    const int nbase = (w >> 1) * 104;
    float acc[13][4];
    #pragma unroll
    for (int j = 0; j < 13; j++)
        #pragma unroll
        for (int r = 0; r < 4; r++) acc[j][r] = 0.f;

    const int lr2 = lane & 7, selA = (lane >> 3) & 1, khA = lane >> 4;
    const int lrB = lane & 15, lhB = lane >> 4;

    #pragma unroll
    for (int ks = 0; ks < 5; ks++) {
        uint32_t af[4];
        ldsm_x4_t(af, smem_u32(Qs + (ks * 16 + khA * 8 + lr2) * 40 + m0 + selA * 8));
        #pragma unroll
        for (int jj = 0; jj < 7; jj++) {
            uint32_t bfr[4];
            ldsm_x4_t(bfr, smem_u32(Ks + (ks * 16 + lrB) * KS_PITCH + nbase + jj * 16 + lhB * 8));
            mma_bf16(acc[2 * jj], af, bfr);
            if (2 * jj + 1 < 13) mma_bf16(acc[2 * jj + 1], af, bfr + 2);
        }
    }
    __syncthreads();

    const int g  = lane >> 2;
    const int c2 = (lane & 3) << 1;
    #pragma unroll
    for (int j = 0; j < 13; j++) {
        int col = nbase + j * 8 + c2;
        *(float2*)&Sc[(m0 + g) * SC_PITCH + col]     = make_float2(acc[j][0], acc[j][1]);
        *(float2*)&Sc[(m0 + 8 + g) * SC_PITCH + col] = make_float2(acc[j][2], acc[j][3]);
    }
    __syncthreads();

    float k2v[13];
    int   mv[13];
    #pragma unroll
    for (int j = 0; j < 13; j++) {
        int s = lane + 32 * j;
        k2v[j] = (s < 400) ? k2s[b * 400 + s] : 0.f;
        mv[j]  = (s < 400) ? msk_in[b * 400 + s] : 1;
    }

    #pragma unroll
    for (int rr = 0; rr < 4; rr++) {
        const int trow = 4 * w + rr;
        const int t    = t0 + trow;
        const float q2v = q2s[b * 1600 + t];

        float x[13], e[13];
        float mx = NINF;
        #pragma unroll
        for (int j = 0; j < 13; j++) {
            int s = lane + 32 * j;
            float qk = Sc[trow * SC_PITCH + s];
            x[j] = (s < 400) ? (-TEMP * (q2v + k2v[j] - 2.f * qk)) : NINF;
            mx = fmaxf(mx, x[j]);
        }
        #pragma unroll
        for (int o = 16; o > 0; o >>= 1) mx = fmaxf(mx, __shfl_xor_sync(0xffffffffu, mx, o));

        float se = 0.f;
        #pragma unroll
        for (int j = 0; j < 13; j++) {
            e[j] = __expf(x[j] - mx);
            se += e[j];
        }
        #pragma unroll
        for (int o = 16; o > 0; o >>= 1) se += __shfl_xor_sync(0xffffffffu, se, o);
        const float lse_m = __logf(se);

        const float* pr = prior    + ((size_t)b * 1600 + t) * 400;
        float* lp_out   = logp_out + ((size_t)b * 1600 + t) * 400;
        float* at_out   = attn_out + ((size_t)b * 1600 + t) * 400;

        float s2 = 0.f;
        #pragma unroll
        for (int j = 0; j < 13; j++) {
            int s = lane + 32 * j;
            if (s < 400) {
                float pv = pr[s] + 1e-8f;
                float lp = x[j] - mx - lse_m + __logf(pv);
                lp_out[s] = lp;
                e[j] = mv[j] ? 0.f : e[j] * pv;
            } else {
                e[j] = 0.f;
            }
            s2 += e[j];
        }
        #pragma unroll
        for (int o = 16; o > 0; o >>= 1) s2 += __shfl_xor_sync(0xffffffffu, s2, o);
        const float inv = 1.f / s2;
        #pragma unroll
        for (int j = 0; j < 13; j++) {
            int s = lane + 32 * j;
            if (s < 400) at_out[s] = e[j] * inv;
        }
    }
}

// ---------------- launch ----------------
extern "C" void kernel_launch(void* const* d_in, const int* in_sizes, int n_in,
                              void* d_out, int out_size)
{
    const float* queries = (const float*)d_in[0];
    const float* keys    = (const float*)d_in[1];
    const int*   mask    = (const int*)d_in[2];
    const float* prior   = (const float*)d_in[3];
    const float* se      = (const float*)d_in[4];
    const float* Wk1     = (const float*)d_in[5];
    const float* bk1     = (const float*)d_in[6];
    const float* Wk2     = (const float*)d_in[7];
    const float* bk2     = (const float*)d_in[8];
    const float* Wq1     = (const float*)d_in[9];
    const float* bq1     = (const float*)d_in[10];
    const float* Wq2     = (const float*)d_in[11];
    const float* bq2     = (const float*)d_in[12];
    const float* Wq3     = (const float*)d_in[13];
    const float* bq3     = (const float*)d_in[14];
    const float* Wks     = (const float*)d_in[15];
    const float* bks     = (const float*)d_in[16];
    const float* Wqs     = (const float*)d_in[17];
    const float* bqs     = (const float*)d_in[18];
    float* out = (float*)d_out;

    float *kb, *qb, *k2s, *q2s;
    bf16 *keys3, *que3, *pWk1, *pWk2, *pWq1, *pWq2, *pWq3, *k1b, *q1b, *q2b, *kfb, *qfb;
    cudaGetSymbolAddress((void**)&kb,    g_kb);
    cudaGetSymbolAddress((void**)&qb,    g_qb);
    cudaGetSymbolAddress((void**)&keys3, g_keys3);
    cudaGetSymbolAddress((void**)&que3,  g_que3);
    cudaGetSymbolAddress((void**)&pWk1,  g_pWk1);
    cudaGetSymbolAddress((void**)&pWk2,  g_pWk2);
    cudaGetSymbolAddress((void**)&pWq1,  g_pWq1);
    cudaGetSymbolAddress((void**)&pWq2,  g_pWq2);
    cudaGetSymbolAddress((void**)&pWq3,  g_pWq3);
    cudaGetSymbolAddress((void**)&k1b,   g_k1b);
    cudaGetSymbolAddress((void**)&q1b,   g_q1b);
    cudaGetSymbolAddress((void**)&q2b,   g_q2b);
    cudaGetSymbolAddress((void**)&kfb,   g_kfb);
    cudaGetSymbolAddress((void**)&qfb,   g_qfb);
    cudaGetSymbolAddress((void**)&k2s,   g_k2s);
    cudaGetSymbolAddress((void**)&q2s,   g_q2s);

    float* attn_out = out;
    float* logp_out = out + (size_t)B_ * T1_ * T2_;

    // attribute setup (idempotent, graph-safe)
    cudaFuncSetAttribute(gemm128_kernel<3, true>,  cudaFuncAttributeMaxDynamicSharedMemorySize, G_SMEM);
    cudaFuncSetAttribute(gemm128_kernel<1, true>,  cudaFuncAttributeMaxDynamicSharedMemorySize, G_SMEM);
    cudaFuncSetAttribute(gemm128_kernel<1, false>, cudaFuncAttributeMaxDynamicSharedMemorySize, G_SMEM);
    cudaFuncSetAttribute(attn_mma_kernel, cudaFuncAttributeMaxDynamicSharedMemorySize, ATTN_SMEM);

    // launches 0-4 (prep; ncu -s 5 lands on the Wk1 GEMM below)
    bias_proj_kernel<<<dim3(CTXT / 8, B_), 256>>>(se, Wks, bks, kb, CTXT, CTXT);                 // 0
    bias_proj_kernel<<<dim3((CMEL + 7) / 8, B_), 256>>>(se, Wqs, bqs, qb, CTXT, CMEL);           // 1
    pack_all_kernel<<<(NPK_TOT + 255) / 256, 256>>>(Wk1, Wq1, Wk2, Wq2, Wq3,
                                                    pWk1, pWq1, pWk2, pWq2, pWq3);               // 2
    prep_x3v_kernel<T2_, CTXT><<<(B_ * CTXT * (T2_ / 8) + 255) / 256, 256>>>(keys, kb, keys3);   // 3
    prep_x3v_kernel<T1_, CMEL><<<(B_ * CMEL * (T1_ / 8) + 255) / 256, 256>>>(queries, qb, que3); // 4

    // key path (per-batch z-grid, no divisions — r13 form)
    gemm128_kernel<3, true ><<<dim3((T2_ + 127) / 128, 8, B_), 256, G_SMEM>>>(pWk1, keys3, bk1, k1b, CTXT, 1024, 1536, T2_);  // 5 (profiled)
    gemm128_kernel<1, false><<<dim3((T2_ + 127) / 128, 1, B_), 256, G_SMEM>>>(pWk2, k1b, bk2, kfb, 1024, 80, 1024, T2_);      // 6

    // query path
    gemm128_kernel<3, true ><<<dim3((T1_ + 127) / 128, 2, B_), 256, G_SMEM>>>(pWq1, que3, bq1, q1b, CMEL, 160, 240, T1_);     // 7
    gemm128_kernel<1, true ><<<dim3((T1_ + 127) / 128, 1, B_), 256, G_SMEM>>>(pWq2, q1b, bq2, q2b, 160, 80, 160, T1_);        // 8
    gemm128_kernel<1, false><<<dim3((T1_ + 127) / 128, 1, B_), 256, G_SMEM>>>(pWq3, q2b, bq3, qfb, 80, 80, 80, T1_);          // 9

    // norms (fused)
    sumsq_both_kernel<<<dim3((T2_ + T1_ + 255) / 256, B_), 256>>>(kfb, qfb, k2s, q2s);           // 10

    // fused attention epilogue (tensor-core qk)
    attn_mma_kernel<<<dim3(T1_ / 32, B_), 256, ATTN_SMEM>>>(qfb, kfb, q2s, k2s, prior, mask, attn_out, logp_out);             // 11
}